// round 9
// baseline (speedup 1.0000x reference)
#include <cuda_runtime.h>
#include <stdint.h>

// Problem constants (fixed by setup_inputs):
//   kv_cache: (NUM_LAYERS=8, 2, B=4, H=8, L=2048, D=128) fp32
//   new_kv:   (8, 2, 4, 8, 1, 128) fp32
//   position_ids: (4, 1) — stored as int32 (JAX x64 disabled downcasts int64)
//   seq_len = 1024
// out = kv_cache[..., :1024, :] with row s==pos[b] replaced by new_kv
// (update visible only when pos[b] < 1024).
//
// R9 strategy: the SM LSU path is pinned at ~6.3 TB/s (LTS cap) across three
// measurements. Move the bulk stream to the COPY ENGINE via one pitched 2D
// D2D memcpy (512 rows x 512KB contiguous), then scatter the 512 updated rows
// (256 KB total) with a tiny kernel.

#define L_FULL   2048
#define S_OUT    1024
#define D_DIM    128
#define B_DIM    4
#define ROWBLKS  512                       // 8*2*4*8 (l,kv,b,h)
#define F4_PER_ROW     (D_DIM / 4)         // 32
#define F4_PER_BLK_OUT (S_OUT * F4_PER_ROW)   // 32768
#define ROW_BYTES_OUT  ((size_t)S_OUT * D_DIM * sizeof(float))   // 524288
#define ROW_BYTES_IN   ((size_t)L_FULL * D_DIM * sizeof(float))  // 1048576

// Scatter: 512 rowblks * 32 float4 = 16384 threads
__global__ void __launch_bounds__(256)
kv_scatter_kernel(const float4* __restrict__ newkv,
                  const int* __restrict__ pos,
                  float4* __restrict__ out)
{
    const unsigned t = blockIdx.x * blockDim.x + threadIdx.x;   // < 16384
    const unsigned d4     = t & (F4_PER_ROW - 1);
    const unsigned rowblk = t >> 5;                              // 0..511
    const unsigned b      = (rowblk >> 3) & (B_DIM - 1);
    const int p = __ldg(&pos[b]);
    if (p >= 0 && p < S_OUT) {
        out[(size_t)rowblk * F4_PER_BLK_OUT + (size_t)p * F4_PER_ROW + d4] =
            __ldg(&newkv[rowblk * F4_PER_ROW + d4]);
    }
}

extern "C" void kernel_launch(void* const* d_in, const int* in_sizes, int n_in,
                              void* d_out, int out_size)
{
    const void*   cache = d_in[0];
    const float4* newkv = (const float4*)d_in[1];
    const int*    pos   = (const int*)d_in[2];

    // Bulk slice copy on the copy engine: for each of the 512 (l,kv,b,h)
    // blocks, copy the first 1024*128 floats (contiguous 512 KB) out of the
    // 2048*128-float source block.
    cudaMemcpy2DAsync(d_out, ROW_BYTES_OUT,
                      cache, ROW_BYTES_IN,
                      ROW_BYTES_OUT,          // width (bytes)
                      ROWBLKS,                // height
                      cudaMemcpyDeviceToDevice, 0);

    // Overwrite the updated rows (runs after the memcpy on the same stream).
    kv_scatter_kernel<<<(ROWBLKS * F4_PER_ROW) / 256, 256, 0, 0>>>(
        newkv, pos, (float4*)d_out);
}

// round 11
// speedup vs baseline: 3.3251x; 3.3251x over previous
#include <cuda_runtime.h>
#include <stdint.h>

// Problem constants (fixed by setup_inputs):
//   kv_cache: (NUM_LAYERS=8, 2, B=4, H=8, L=2048, D=128) fp32
//   new_kv:   (8, 2, 4, 8, 1, 128) fp32
//   position_ids: (4, 1) — stored as int32 (JAX x64 disabled downcasts int64)
//   seq_len = 1024
// out = kv_cache[..., :1024, :] with row s==pos[b] replaced by new_kv.
//
// FINAL (R4 config — best measured): single fused streaming kernel.
//   - one float4 store per output element, fully coalesced both streams
//   - MLP_p1=2 per thread (R6 showed MLP=4 regresses via cross-CTA
//     L1tex-queue spread; R8 showed .cs hints are <= neutral)
//   - scatter fused as a predicated overwrite on the rare matching row
// Measured: 75.5us kernel, 6.4 TB/s (78.4% of spec) — at the LTS-cap
// plateau for a 1:1 fp32 read:write stream (copy engine measured 3.3x
// slower; TMA shares the same cap per path-independence).

#define L_FULL   2048
#define S_OUT    1024
#define D_DIM    128
#define B_DIM    4
#define ROWBLKS  512            // 8 * 2 * 4 * 8  (l,kv,b,h) combined
#define F4_PER_ROW   (D_DIM / 4)        // 32
#define F4_PER_BLK_OUT (S_OUT * F4_PER_ROW)   // 32768
#define F4_PER_BLK_IN  (L_FULL * F4_PER_ROW)  // 65536
#define TOTAL_F4 (ROWBLKS * F4_PER_BLK_OUT)   // 16,777,216

#define THREADS   256
#define F4_PER_THREAD 2
#define GRID      (TOTAL_F4 / (THREADS * F4_PER_THREAD))   // 32768 blocks

__global__ void __launch_bounds__(THREADS)
kv_slice_update_kernel(const float4* __restrict__ cache,
                       const float4* __restrict__ newkv,
                       const int* __restrict__ pos,
                       float4* __restrict__ out)
{
    const unsigned base = blockIdx.x * (THREADS * F4_PER_THREAD) + threadIdx.x;

    float4 v[F4_PER_THREAD];

#pragma unroll
    for (int j = 0; j < F4_PER_THREAD; ++j) {
        const unsigned i4 = base + j * THREADS;
        const unsigned d4     = i4 & (F4_PER_ROW - 1);
        const unsigned s      = (i4 >> 5) & (S_OUT - 1);
        const unsigned rowblk = i4 >> 15;
        v[j] = __ldg(&cache[(size_t)rowblk * F4_PER_BLK_IN
                            + (size_t)s * F4_PER_ROW + d4]);
    }

#pragma unroll
    for (int j = 0; j < F4_PER_THREAD; ++j) {
        const unsigned i4     = base + j * THREADS;
        const unsigned d4     = i4 & (F4_PER_ROW - 1);
        const unsigned s      = (i4 >> 5) & (S_OUT - 1);
        const unsigned rowblk = i4 >> 15;
        const unsigned b      = (rowblk >> 3) & (B_DIM - 1);
        const int p = __ldg(&pos[b]);
        if ((int)s == p) {
            v[j] = __ldg(&newkv[rowblk * F4_PER_ROW + d4]);
        }
        out[i4] = v[j];
    }
}

extern "C" void kernel_launch(void* const* d_in, const int* in_sizes, int n_in,
                              void* d_out, int out_size)
{
    const float4* cache = (const float4*)d_in[0];
    const float4* newkv = (const float4*)d_in[1];
    const int*    pos   = (const int*)d_in[2];
    float4*       out   = (float4*)d_out;

    kv_slice_update_kernel<<<GRID, THREADS>>>(cache, newkv, pos, out);
}